// round 14
// baseline (speedup 1.0000x reference)
#include <cuda_runtime.h>

// Problem constants (fixed by dataset)
#define D_MODEL 1024
#define ADAPT   128
#define NUM_LIB 8
#define NPAIR   64
#define MAXB    1024
#define KC      8        // k-split for gemm1 (128 k per CTA)
#define KCH     128
#define DC      64       // d-cols per gemm2 CTA
#define HC      64       // a-cols per gemm1 CTA
#define NST     16       // stages per slab (8 lines x 64 cols = 2 KB each)
#define RT      32       // row capacity per tile
#define RING    6        // cp.async ring depth

typedef unsigned long long ull;

// Packed fp32x2 ops (sm_10x)
#define FMA2(d,a,b,c) asm("fma.rn.f32x2 %0, %1, %2, %3;":"=l"(d):"l"(a),"l"(b),"l"(c))
#define PACK2(d,s)    asm("mov.b64 %0, {%1, %1};":"=l"(d):"f"(s))
// cp.async 16B, L1-bypass
#define CP16(dst,src) asm volatile("cp.async.cg.shared.global [%0], [%1], 16;"::"r"(dst),"l"(src))
#define CPCOMMIT()    asm volatile("cp.async.commit_group;")
#define CPWAIT4()     asm volatile("cp.async.wait_group 4;")

// Device scratch (no allocations allowed)
__device__ int   g_cnt[NPAIR];
__device__ int   g_rows[NPAIR][MAXB];
__device__ float g_hp[KC][MAXB * ADAPT];   // K-split partial pre-activations
__device__ float g_h[MAXB * ADAPT];        // relu(sum + b1)

// ---------------------------------------------------------------------------
__global__ void k_build(const int* __restrict__ src, const int* __restrict__ tgt, int B) {
    int t = threadIdx.x;
    if (t < NPAIR) g_cnt[t] = 0;
    __syncthreads();
    if (t < B) {
        int s = src[t], g = tgt[t];
        if (s != g) {
            int p = s * NUM_LIB + g;
            int slot = atomicAdd(&g_cnt[p], 1);
            g_rows[p][slot] = t;
        }
    }
}

// ---------------------------------------------------------------------------
// k_actcopy: one warp per row. Identity rows: out = x. Translate rows:
// g_h = relu(sum_kz g_hp + b1). Grid 128 x 256.
// ---------------------------------------------------------------------------
__global__ void __launch_bounds__(256)
k_actcopy(const float* __restrict__ x,
          const int* __restrict__ src, const int* __restrict__ tgt,
          const float* __restrict__ b1, float* __restrict__ out) {
    int idx = blockIdx.x * 256 + threadIdx.x;
    int row = idx >> 5;
    int q   = idx & 31;
    int s = src[row], g = tgt[row];
    if (s == g) {
        const float4* xi = (const float4*)(x + (size_t)row * D_MODEL);
        float4* yo = (float4*)(out + (size_t)row * D_MODEL);
        #pragma unroll
        for (int j = 0; j < 8; j++) yo[q + 32 * j] = xi[q + 32 * j];
    } else {
        int p = s * NUM_LIB + g;
        size_t off = (size_t)row * ADAPT + q * 4;
        float4 v = make_float4(0.f, 0.f, 0.f, 0.f);
        #pragma unroll
        for (int kz = 0; kz < KC; kz++) {
            float4 u = *(const float4*)(g_hp[kz] + off);
            v.x += u.x; v.y += u.y; v.z += u.z; v.w += u.w;
        }
        float4 b = *(const float4*)(b1 + p * ADAPT + q * 4);
        v.x = fmaxf(v.x + b.x, 0.f); v.y = fmaxf(v.y + b.y, 0.f);
        v.z = fmaxf(v.z + b.z, 0.f); v.w = fmaxf(v.w + b.w, 0.f);
        *(float4*)(g_h + off) = v;
    }
}

// ---------------------------------------------------------------------------
// GEMM1: g_hp[kz][row, ah*64 + 2l..] = x[row, kz*128:+128] . W1 slab
// grid (64, 16): y = kz*2 + ah. 128 thr: lane l owns a-pair, warp rg -> 8 rows.
// Weights: depth-6 cp.async ring, 2 KB stages, LDS.64 consumption.
// x duplicated as f32x2 in smem [k][32 rows] (pure broadcast consumption).
// ---------------------------------------------------------------------------
__global__ void __launch_bounds__(128, 5)
k_gemm1(const float* __restrict__ x, const float* __restrict__ W1) {
    extern __shared__ __align__(16) char smx[];
    ull*   xs2 = (ull*)smx;                     // [128 k][32 r] dup pairs (32 KB)
    float* ws  = (float*)(smx + KCH * RT * 8);  // ring [6][8*64] (12 KB)
    int p  = blockIdx.x;
    int kz = blockIdx.y >> 1;
    int ah = blockIdx.y & 1;
    int n = g_cnt[p];
    if (n == 0) return;
    int t  = threadIdx.x;
    int l  = t & 31;
    int rg = t >> 5;
    const int* rows = g_rows[p];
    const float* Wb = W1 + ((size_t)p * D_MODEL + (size_t)kz * KCH) * ADAPT + ah * HC;
    float* hp = g_hp[kz];
    unsigned wsb = (unsigned)__cvta_generic_to_shared(ws);
    int wln = t >> 4;                 // cp.async: line 0..7
    int wc  = (t & 15) * 4;           // col (floats); smem off = t*16

    for (int base = 0; base < n; base += RT) {
        int nn = min(RT, n - base);
        __syncthreads();              // previous tile fully consumed
        // prologue: stages 0..4 (2 KB each, 1 CP16 per thread)
        #pragma unroll
        for (int s = 0; s < RING - 1; s++) {
            CP16(wsb + s * 2048u + (unsigned)t * 16u,
                 (const float4*)(Wb + (size_t)(s * 8 + wln) * ADAPT + wc));
            CPCOMMIT();
        }
        // stage x dup pairs [k][row]: lane = row, warp rg covers k [rg*32,+32)
        {
            int rr = min(l, nn - 1);          // clamp: garbage rows never stored
            const float4* xr = (const float4*)
                (x + (size_t)rows[base + rr] * D_MODEL + kz * KCH + rg * 32);
            #pragma unroll
            for (int c = 0; c < 8; c++) {
                float4 u = xr[c];
                ull q0, q1, q2, q3;
                PACK2(q0, u.x); PACK2(q1, u.y); PACK2(q2, u.z); PACK2(q3, u.w);
                int k = rg * 32 + c * 4;
                xs2[(k + 0) * RT + l] = q0; xs2[(k + 1) * RT + l] = q1;
                xs2[(k + 2) * RT + l] = q2; xs2[(k + 3) * RT + l] = q3;
            }
        }
        ull acc[8];
        #pragma unroll
        for (int j = 0; j < 8; j++) acc[j] = 0;
        bool active = (rg * 8 < nn);
        int cons = 0, prod = RING - 1;

        #pragma unroll 1
        for (int s = 0; s < NST; s++) {
            CPWAIT4();
            __syncthreads();
            if (s + RING - 1 < NST)
                CP16(wsb + prod * 2048u + (unsigned)t * 16u,
                     (const float4*)(Wb + (size_t)((s + RING - 1) * 8 + wln) * ADAPT + wc));
            CPCOMMIT();               // unconditional: uniform group indexing
            if (active) {
                const float* wl = ws + cons * (8 * HC);
                const ull* xb = xs2 + (s * 8) * RT + rg * 8;
                #pragma unroll
                for (int kk = 0; kk < 8; kk++) {
                    ull w = *(const ull*)(wl + kk * HC + l * 2);
                    const ull* xr8 = xb + kk * RT;
                    ulonglong2 x01 = *(const ulonglong2*)(xr8);
                    ulonglong2 x23 = *(const ulonglong2*)(xr8 + 2);
                    ulonglong2 x45 = *(const ulonglong2*)(xr8 + 4);
                    ulonglong2 x67 = *(const ulonglong2*)(xr8 + 6);
                    FMA2(acc[0], w, x01.x, acc[0]); FMA2(acc[1], w, x01.y, acc[1]);
                    FMA2(acc[2], w, x23.x, acc[2]); FMA2(acc[3], w, x23.y, acc[3]);
                    FMA2(acc[4], w, x45.x, acc[4]); FMA2(acc[5], w, x45.y, acc[5]);
                    FMA2(acc[6], w, x67.x, acc[6]); FMA2(acc[7], w, x67.y, acc[7]);
                }
            }
            if (++cons == RING) cons = 0;
            if (++prod == RING) prod = 0;
        }
        #pragma unroll
        for (int j = 0; j < 8; j++) {
            int r = rg * 8 + j;
            if (r < nn)
                *(ull*)(hp + (size_t)rows[base + r] * ADAPT + ah * HC + l * 2) = acc[j];
        }
    }
}

// ---------------------------------------------------------------------------
// GEMM2: out[row, dc*64 + 2l..] = g_h[row,:] . W2[p,:,slab] + b2
// grid (64, 16). Same structure; lane owns d-pair, warp -> 8 rows.
// ---------------------------------------------------------------------------
__global__ void __launch_bounds__(128, 5)
k_gemm2(const float* __restrict__ W2, const float* __restrict__ b2,
        float* __restrict__ out) {
    extern __shared__ __align__(16) char smx[];
    ull*   hs2 = (ull*)smx;                      // [128 a][32 r] dup pairs (32 KB)
    float* ws  = (float*)(smx + ADAPT * RT * 8); // ring [6][8*64] (12 KB)
    int p  = blockIdx.x;
    int dc = blockIdx.y;
    int n = g_cnt[p];
    if (n == 0) return;
    int t  = threadIdx.x;
    int l  = t & 31;
    int rg = t >> 5;
    const int* rows = g_rows[p];
    const float* Wb = W2 + (size_t)p * ADAPT * D_MODEL + dc * DC;
    int d0 = dc * DC + l * 2;
    float2 bias = *(const float2*)(b2 + (size_t)p * D_MODEL + d0);
    unsigned wsb = (unsigned)__cvta_generic_to_shared(ws);
    int wln = t >> 4;
    int wc  = (t & 15) * 4;

    for (int base = 0; base < n; base += RT) {
        int nn = min(RT, n - base);
        __syncthreads();
        #pragma unroll
        for (int s = 0; s < RING - 1; s++) {
            CP16(wsb + s * 2048u + (unsigned)t * 16u,
                 (const float4*)(Wb + (size_t)(s * 8 + wln) * D_MODEL + wc));
            CPCOMMIT();
        }
        // stage h dup pairs [a][row]: lane = row, warp rg covers a [rg*32,+32)
        {
            int rr = min(l, nn - 1);
            const float4* hr = (const float4*)
                (g_h + (size_t)rows[base + rr] * ADAPT + rg * 32);
            #pragma unroll
            for (int c = 0; c < 8; c++) {
                float4 u = hr[c];
                ull q0, q1, q2, q3;
                PACK2(q0, u.x); PACK2(q1, u.y); PACK2(q2, u.z); PACK2(q3, u.w);
                int a = rg * 32 + c * 4;
                hs2[(a + 0) * RT + l] = q0; hs2[(a + 1) * RT + l] = q1;
                hs2[(a + 2) * RT + l] = q2; hs2[(a + 3) * RT + l] = q3;
            }
        }
        ull acc[8];
        #pragma unroll
        for (int j = 0; j < 8; j++) acc[j] = 0;
        bool active = (rg * 8 < nn);
        int cons = 0, prod = RING - 1;

        #pragma unroll 1
        for (int s = 0; s < NST; s++) {
            CPWAIT4();
            __syncthreads();
            if (s + RING - 1 < NST)
                CP16(wsb + prod * 2048u + (unsigned)t * 16u,
                     (const float4*)(Wb + (size_t)((s + RING - 1) * 8 + wln) * D_MODEL + wc));
            CPCOMMIT();
            if (active) {
                const float* wl = ws + cons * (8 * DC);
                const ull* hb = hs2 + (s * 8) * RT + rg * 8;
                #pragma unroll
                for (int kk = 0; kk < 8; kk++) {
                    ull w = *(const ull*)(wl + kk * DC + l * 2);
                    const ull* hr8 = hb + kk * RT;
                    ulonglong2 h01 = *(const ulonglong2*)(hr8);
                    ulonglong2 h23 = *(const ulonglong2*)(hr8 + 2);
                    ulonglong2 h45 = *(const ulonglong2*)(hr8 + 4);
                    ulonglong2 h67 = *(const ulonglong2*)(hr8 + 6);
                    FMA2(acc[0], w, h01.x, acc[0]); FMA2(acc[1], w, h01.y, acc[1]);
                    FMA2(acc[2], w, h23.x, acc[2]); FMA2(acc[3], w, h23.y, acc[3]);
                    FMA2(acc[4], w, h45.x, acc[4]); FMA2(acc[5], w, h45.y, acc[5]);
                    FMA2(acc[6], w, h67.x, acc[6]); FMA2(acc[7], w, h67.y, acc[7]);
                }
            }
            if (++cons == RING) cons = 0;
            if (++prod == RING) prod = 0;
        }
        #pragma unroll
        for (int j = 0; j < 8; j++) {
            int r = rg * 8 + j;
            if (r < nn) {
                float2 f = *(float2*)&acc[j];
                f.x += bias.x; f.y += bias.y;
                *(float2*)(out + (size_t)rows[base + r] * D_MODEL + d0) = f;
            }
        }
    }
}

// ---------------------------------------------------------------------------
#define SMEM1 (KCH * RT * 8 + RING * 8 * HC * 4)    // 32768 + 12288 = 45056
#define SMEM2 (ADAPT * RT * 8 + RING * 8 * DC * 4)  // 45056

extern "C" void kernel_launch(void* const* d_in, const int* in_sizes, int n_in,
                              void* d_out, int out_size) {
    const float* x   = (const float*)d_in[0];
    const int*   src = (const int*)d_in[1];
    const int*   tgt = (const int*)d_in[2];
    const float* W1  = (const float*)d_in[3];
    const float* b1  = (const float*)d_in[4];
    const float* W2  = (const float*)d_in[5];
    const float* b2  = (const float*)d_in[6];
    float* out = (float*)d_out;
    int B = in_sizes[1];  // 1024

    cudaFuncSetAttribute(k_gemm1, cudaFuncAttributeMaxDynamicSharedMemorySize, SMEM1);
    cudaFuncSetAttribute(k_gemm2, cudaFuncAttributeMaxDynamicSharedMemorySize, SMEM2);

    k_build<<<1, 1024>>>(src, tgt, B);
    k_gemm1<<<dim3(NPAIR, 16), 128, SMEM1>>>(x, W1);
    k_actcopy<<<128, 256>>>(x, src, tgt, b1, out);
    k_gemm2<<<dim3(NPAIR, 16), 128, SMEM2>>>(W2, b2, out);
}

// round 15
// speedup vs baseline: 1.5014x; 1.5014x over previous
#include <cuda_runtime.h>

// Problem constants (fixed by dataset)
#define D_MODEL 1024
#define ADAPT   128
#define NUM_LIB 8
#define NPAIR   64
#define MAXB    1024
#define KC      8        // k-split for gemm1 (128 k per CTA)
#define KCH     128
#define DC      128      // d-cols per gemm2 CTA
#define NST     16       // stages per slab (8 lines x 128 cols = 4 KB each)
#define RT      32       // row capacity per tile (covers whole pair)
#define RSF     36       // float stride per k/a line (aligned, 2-way STS)
#define RING    6        // cp.async ring depth

typedef unsigned long long ull;

// Packed fp32x2 ops (sm_10x)
#define FMA2(d,a,b,c) asm("fma.rn.f32x2 %0, %1, %2, %3;":"=l"(d):"l"(a),"l"(b),"l"(c))
#define PACK2(d,s)    asm("mov.b64 %0, {%1, %1};":"=l"(d):"f"(s))
#define UNPK2(lo,hi,s) asm("mov.b64 {%0, %1}, %2;":"=f"(lo),"=f"(hi):"l"(s))
// cp.async 16B, L1-bypass
#define CP16(dst,src) asm volatile("cp.async.cg.shared.global [%0], [%1], 16;"::"r"(dst),"l"(src))
#define CPCOMMIT()    asm volatile("cp.async.commit_group;")
#define CPWAIT4()     asm volatile("cp.async.wait_group 4;")

// Device scratch (no allocations allowed)
__device__ int   g_cnt[NPAIR];
__device__ int   g_rows[NPAIR][MAXB];
__device__ float g_hp[KC][MAXB * ADAPT];   // K-split partial pre-activations
__device__ float g_h[MAXB * ADAPT];        // relu(sum + b1)

// ---------------------------------------------------------------------------
__global__ void k_build(const int* __restrict__ src, const int* __restrict__ tgt, int B) {
    int t = threadIdx.x;
    if (t < NPAIR) g_cnt[t] = 0;
    __syncthreads();
    if (t < B) {
        int s = src[t], g = tgt[t];
        if (s != g) {
            int p = s * NUM_LIB + g;
            int slot = atomicAdd(&g_cnt[p], 1);
            g_rows[p][slot] = t;
        }
    }
}

// ---------------------------------------------------------------------------
// k_actcopy: one warp per row. Identity rows: out = x. Translate rows:
// g_h = relu(sum_kz g_hp + b1). Grid 128 x 256.
// ---------------------------------------------------------------------------
__global__ void __launch_bounds__(256)
k_actcopy(const float* __restrict__ x,
          const int* __restrict__ src, const int* __restrict__ tgt,
          const float* __restrict__ b1, float* __restrict__ out) {
    int idx = blockIdx.x * 256 + threadIdx.x;
    int row = idx >> 5;
    int q   = idx & 31;
    int s = src[row], g = tgt[row];
    if (s == g) {
        const float4* xi = (const float4*)(x + (size_t)row * D_MODEL);
        float4* yo = (float4*)(out + (size_t)row * D_MODEL);
        #pragma unroll
        for (int j = 0; j < 8; j++) yo[q + 32 * j] = xi[q + 32 * j];
    } else {
        int p = s * NUM_LIB + g;
        size_t off = (size_t)row * ADAPT + q * 4;
        float4 v = make_float4(0.f, 0.f, 0.f, 0.f);
        #pragma unroll
        for (int kz = 0; kz < KC; kz++) {
            float4 u = *(const float4*)(g_hp[kz] + off);
            v.x += u.x; v.y += u.y; v.z += u.z; v.w += u.w;
        }
        float4 b = *(const float4*)(b1 + p * ADAPT + q * 4);
        v.x = fmaxf(v.x + b.x, 0.f); v.y = fmaxf(v.y + b.y, 0.f);
        v.z = fmaxf(v.z + b.z, 0.f); v.w = fmaxf(v.w + b.w, 0.f);
        *(float4*)(g_h + off) = v;
    }
}

// ---------------------------------------------------------------------------
// GEMM1 (k-split): g_hp[kz][row, a] = x[row, kz*128:+128] . W1[p, slice, a]
// grid (64, 8), 256 thr. Thread: a-quad tq = t&31, warp rg = t>>5 -> 4 rows.
// acc packs ROW pairs (x read as natural ull pairs); weights PACK2'd.
// Depth-6 cp.async weight ring; x staged as plain floats [k][row] (RSF=36).
// ---------------------------------------------------------------------------
__global__ void __launch_bounds__(256, 3)
k_gemm1(const float* __restrict__ x, const float* __restrict__ W1) {
    extern __shared__ __align__(16) char smx[];
    float* xs = (float*)smx;                      // [128 k][RSF] (18 KB)
    float* ws = (float*)(smx + KCH * RSF * 4);    // ring [6][8*128] (24 KB)
    int p  = blockIdx.x;
    int kz = blockIdx.y;
    int n = g_cnt[p];
    if (n == 0) return;
    int t  = threadIdx.x;
    int tq = t & 31;                  // a-quad (a0 = tq*4)
    int rg = t >> 5;                  // warp -> rows rg*4..+3
    int js = t & 7;                   // staging k residue
    int rs = t >> 3;                  // staging row 0..31
    const int* rows = g_rows[p];
    const float* Wb = W1 + ((size_t)p * D_MODEL + (size_t)kz * KCH) * ADAPT;
    float* hp = g_hp[kz];
    unsigned wsb = (unsigned)__cvta_generic_to_shared(ws);

    for (int base = 0; base < n; base += RT) {
        int nn = min(RT, n - base);
        __syncthreads();              // previous tile fully consumed
        // prologue: weight stages 0..4 (each 4 KB = 256 float4, 1 per thread)
        #pragma unroll
        for (int s = 0; s < RING - 1; s++) {
            const float4* g = (const float4*)(Wb + (size_t)s * 8 * ADAPT);
            CP16(wsb + s * 4096u + (unsigned)t * 16u, g + t);
            CPCOMMIT();
        }
        // stage x plain floats [k][row]; thread: row rs, k = js + 8c
        {
            const float* xr = (rs < nn)
                ? x + (size_t)rows[base + rs] * D_MODEL + kz * KCH : 0;
            #pragma unroll
            for (int c = 0; c < 16; c++) {
                int k = js + 8 * c;
                xs[k * RSF + rs] = (rs < nn) ? xr[k] : 0.f;
            }
        }
        ull acc[8];                   // [a 0..3][row-pair 0..1]
        #pragma unroll
        for (int j = 0; j < 8; j++) acc[j] = 0;
        bool active = (rg * 4 < nn);
        int cons = 0, prod = RING - 1;

        #pragma unroll 1
        for (int s = 0; s < NST; s++) {
            CPWAIT4();
            __syncthreads();
            if (s + RING - 1 < NST) {
                const float4* g = (const float4*)(Wb + (size_t)(s + RING - 1) * 8 * ADAPT);
                CP16(wsb + prod * 4096u + (unsigned)t * 16u, g + t);
            }
            CPCOMMIT();               // unconditional: uniform group indexing
            if (active) {
                const float* wl = ws + cons * (8 * ADAPT);
                const float* xb = xs + (s * 8) * RSF + rg * 4;
                #pragma unroll
                for (int kk = 0; kk < 8; kk++) {
                    float4 w = *(const float4*)(wl + kk * ADAPT + tq * 4);
                    ulonglong2 x01 = *(const ulonglong2*)(xb + kk * RSF);
                    ull W0, W1d, W2d, W3d;
                    PACK2(W0, w.x); PACK2(W1d, w.y); PACK2(W2d, w.z); PACK2(W3d, w.w);
                    FMA2(acc[0], W0,  x01.x, acc[0]); FMA2(acc[1], W0,  x01.y, acc[1]);
                    FMA2(acc[2], W1d, x01.x, acc[2]); FMA2(acc[3], W1d, x01.y, acc[3]);
                    FMA2(acc[4], W2d, x01.x, acc[4]); FMA2(acc[5], W2d, x01.y, acc[5]);
                    FMA2(acc[6], W3d, x01.x, acc[6]); FMA2(acc[7], W3d, x01.y, acc[7]);
                }
            }
            if (++cons == RING) cons = 0;
            if (++prod == RING) prod = 0;
        }
        // epilogue: transpose in-register -> coalesced float4 per row
        #pragma unroll
        for (int rp = 0; rp < 2; rp++) {
            float4 ve, vo;
            UNPK2(ve.x, vo.x, acc[0 + rp]);
            UNPK2(ve.y, vo.y, acc[2 + rp]);
            UNPK2(ve.z, vo.z, acc[4 + rp]);
            UNPK2(ve.w, vo.w, acc[6 + rp]);
            int r0 = rg * 4 + rp * 2;
            if (r0 < nn)
                *(float4*)(hp + (size_t)rows[base + r0] * ADAPT + tq * 4) = ve;
            if (r0 + 1 < nn)
                *(float4*)(hp + (size_t)rows[base + r0 + 1] * ADAPT + tq * 4) = vo;
        }
    }
}

// ---------------------------------------------------------------------------
// GEMM2: out[row, d] = g_h[row,:] . W2[p,:,d] + b2[p,d]
// grid (64, 8), 256 thr. Same structure; d-quad tq, 4 rows per warp.
// ---------------------------------------------------------------------------
__global__ void __launch_bounds__(256, 3)
k_gemm2(const float* __restrict__ W2, const float* __restrict__ b2,
        float* __restrict__ out) {
    extern __shared__ __align__(16) char smx[];
    float* hs = (float*)smx;                      // [128 a][RSF] (18 KB)
    float* ws = (float*)(smx + ADAPT * RSF * 4);  // ring [6][8*128] (24 KB)
    int p  = blockIdx.x;
    int dc = blockIdx.y;
    int n = g_cnt[p];
    if (n == 0) return;
    int t  = threadIdx.x;
    int tq = t & 31;
    int rg = t >> 5;
    int js = t & 7;
    int rs = t >> 3;
    const int* rows = g_rows[p];
    const float* Wb = W2 + (size_t)p * ADAPT * D_MODEL + dc * DC;
    int d0 = dc * DC + tq * 4;
    float4 bias = *(const float4*)(b2 + (size_t)p * D_MODEL + d0);
    unsigned wsb = (unsigned)__cvta_generic_to_shared(ws);
    int wline = t >> 5;               // refill: line 0..7, col = t&31
    int wcol  = t & 31;

    for (int base = 0; base < n; base += RT) {
        int nn = min(RT, n - base);
        __syncthreads();
        #pragma unroll
        for (int s = 0; s < RING - 1; s++) {
            CP16(wsb + s * 4096u + (unsigned)(wline * 32 + wcol) * 16u,
                 (const float4*)(Wb + (size_t)(s * 8 + wline) * D_MODEL) + wcol);
            CPCOMMIT();
        }
        // stage h plain floats [a][row]
        {
            const float* hr = (rs < nn) ? g_h + (size_t)rows[base + rs] * ADAPT : 0;
            #pragma unroll
            for (int c = 0; c < 16; c++) {
                int a = js + 8 * c;
                hs[a * RSF + rs] = (rs < nn) ? hr[a] : 0.f;
            }
        }
        ull acc[8];
        #pragma unroll
        for (int j = 0; j < 8; j++) acc[j] = 0;
        bool active = (rg * 4 < nn);
        int cons = 0, prod = RING - 1;

        #pragma unroll 1
        for (int s = 0; s < NST; s++) {
            CPWAIT4();
            __syncthreads();
            if (s + RING - 1 < NST) {
                int sl = (s + RING - 1) * 8;
                CP16(wsb + prod * 4096u + (unsigned)(wline * 32 + wcol) * 16u,
                     (const float4*)(Wb + (size_t)(sl + wline) * D_MODEL) + wcol);
            }
            CPCOMMIT();
            if (active) {
                const float* wl = ws + cons * (8 * DC);
                const float* hb = hs + (s * 8) * RSF + rg * 4;
                #pragma unroll
                for (int kk = 0; kk < 8; kk++) {
                    float4 w = *(const float4*)(wl + kk * DC + tq * 4);
                    ulonglong2 h01 = *(const ulonglong2*)(hb + kk * RSF);
                    ull W0, W1d, W2d, W3d;
                    PACK2(W0, w.x); PACK2(W1d, w.y); PACK2(W2d, w.z); PACK2(W3d, w.w);
                    FMA2(acc[0], W0,  h01.x, acc[0]); FMA2(acc[1], W0,  h01.y, acc[1]);
                    FMA2(acc[2], W1d, h01.x, acc[2]); FMA2(acc[3], W1d, h01.y, acc[3]);
                    FMA2(acc[4], W2d, h01.x, acc[4]); FMA2(acc[5], W2d, h01.y, acc[5]);
                    FMA2(acc[6], W3d, h01.x, acc[6]); FMA2(acc[7], W3d, h01.y, acc[7]);
                }
            }
            if (++cons == RING) cons = 0;
            if (++prod == RING) prod = 0;
        }
        #pragma unroll
        for (int rp = 0; rp < 2; rp++) {
            float4 ve, vo;
            UNPK2(ve.x, vo.x, acc[0 + rp]);
            UNPK2(ve.y, vo.y, acc[2 + rp]);
            UNPK2(ve.z, vo.z, acc[4 + rp]);
            UNPK2(ve.w, vo.w, acc[6 + rp]);
            ve.x += bias.x; ve.y += bias.y; ve.z += bias.z; ve.w += bias.w;
            vo.x += bias.x; vo.y += bias.y; vo.z += bias.z; vo.w += bias.w;
            int r0 = rg * 4 + rp * 2;
            if (r0 < nn)
                *(float4*)(out + (size_t)rows[base + r0] * D_MODEL + d0) = ve;
            if (r0 + 1 < nn)
                *(float4*)(out + (size_t)rows[base + r0 + 1] * D_MODEL + d0) = vo;
        }
    }
}

// ---------------------------------------------------------------------------
#define SMEM1 (KCH * RSF * 4 + RING * 8 * ADAPT * 4)   // 18432 + 24576 = 43008
#define SMEM2 (ADAPT * RSF * 4 + RING * 8 * DC * 4)    // 43008

extern "C" void kernel_launch(void* const* d_in, const int* in_sizes, int n_in,
                              void* d_out, int out_size) {
    const float* x   = (const float*)d_in[0];
    const int*   src = (const int*)d_in[1];
    const int*   tgt = (const int*)d_in[2];
    const float* W1  = (const float*)d_in[3];
    const float* b1  = (const float*)d_in[4];
    const float* W2  = (const float*)d_in[5];
    const float* b2  = (const float*)d_in[6];
    float* out = (float*)d_out;
    int B = in_sizes[1];  // 1024

    cudaFuncSetAttribute(k_gemm1, cudaFuncAttributeMaxDynamicSharedMemorySize, SMEM1);
    cudaFuncSetAttribute(k_gemm2, cudaFuncAttributeMaxDynamicSharedMemorySize, SMEM2);

    k_build<<<1, 1024>>>(src, tgt, B);
    k_gemm1<<<dim3(NPAIR, KC), 256, SMEM1>>>(x, W1);
    k_actcopy<<<128, 256>>>(x, src, tgt, b1, out);
    k_gemm2<<<dim3(NPAIR, 8), 256, SMEM2>>>(W2, b2, out);
}